// round 1
// baseline (speedup 1.0000x reference)
#include <cuda_runtime.h>
#include <math.h>

// Problem constants (fixed by dataset)
#define BQ    2048          // queries
#define NMEM  100000        // memory rows
#define NPAD  100096        // padded to multiple of 128 (782*128)
#define DDIM  256
#define KTOP  8

// ---------------- scratch (static device globals; no dynamic alloc) --------
__device__ float g_qn[(size_t)BQ * DDIM];        // normalized queries   (2 MB)
__device__ float g_mn[(size_t)NPAD * DDIM];      // normalized memory    (102.5 MB)
__device__ float g_scores[(size_t)BQ * NPAD];    // score matrix         (820 MB)

// ---------------- L2 normalize: one warp per row (D=256 = 64 float4) -------
__device__ __forceinline__ void norm_row(const float* __restrict__ in,
                                         float* __restrict__ out,
                                         int row, int lane) {
    const float4* src = (const float4*)(in + (size_t)row * DDIM);
    float4* dst       = (float4*)(out + (size_t)row * DDIM);
    float4 a = src[lane];
    float4 b = src[lane + 32];
    float ss = a.x*a.x + a.y*a.y + a.z*a.z + a.w*a.w
             + b.x*b.x + b.y*b.y + b.z*b.z + b.w*b.w;
    #pragma unroll
    for (int o = 16; o > 0; o >>= 1) ss += __shfl_xor_sync(0xffffffffu, ss, o);
    float n   = sqrtf(ss);
    float inv = 1.0f / fmaxf(n, 1e-12f);
    a.x *= inv; a.y *= inv; a.z *= inv; a.w *= inv;
    b.x *= inv; b.y *= inv; b.z *= inv; b.w *= inv;
    dst[lane]      = a;
    dst[lane + 32] = b;
}

__global__ void norm_query_kernel(const float* __restrict__ q, int rows) {
    int warp = (blockIdx.x * blockDim.x + threadIdx.x) >> 5;
    int lane = threadIdx.x & 31;
    if (warp >= rows) return;
    norm_row(q, g_qn, warp, lane);
}

__global__ void norm_mem_kernel(const float* __restrict__ m, int rows_valid, int rows_total) {
    int warp = (blockIdx.x * blockDim.x + threadIdx.x) >> 5;
    int lane = threadIdx.x & 31;
    if (warp >= rows_total) return;
    if (warp >= rows_valid) {
        // zero pad rows -> score 0, never reaches top-8 (top scores ~0.25)
        float4 z = make_float4(0.f, 0.f, 0.f, 0.f);
        float4* dst = (float4*)(g_mn + (size_t)warp * DDIM);
        dst[lane] = z; dst[lane + 32] = z;
        return;
    }
    norm_row(m, g_mn, warp, lane);
}

// ---------------- SGEMM: scores = Qn (BQ x D) * Mn^T (NPAD x D) ------------
// 128x128 block tile, BK=16, 256 threads, 8x8 per-thread register tile.
#define BM 128
#define BN 128
#define BK 16
#define TM 8
#define TN 8

__global__ __launch_bounds__(256, 2)
void gemm_kernel() {
    __shared__ float As[BK][BM + 4];
    __shared__ float Bs[BK][BN + 4];

    const int tid = threadIdx.x;
    const int tx  = tid & 15;          // 0..15 -> n
    const int ty  = tid >> 4;          // 0..15 -> m
    const int m0  = blockIdx.x * BM;   // x = query tiles (16) for L2 reuse of B
    const int n0  = blockIdx.y * BN;

    const int lr = tid >> 2;           // 0..63 (row within tile, +64 second half)
    const int lc = (tid & 3) * 4;      // k-offset 0,4,8,12

    float acc[TM][TN];
    #pragma unroll
    for (int i = 0; i < TM; i++)
        #pragma unroll
        for (int j = 0; j < TN; j++) acc[i][j] = 0.f;

    float ar[TM], br[TN];

    for (int k0 = 0; k0 < DDIM; k0 += BK) {
        #pragma unroll
        for (int h = 0; h < 2; h++) {
            int r = lr + h * 64;
            float4 va = *(const float4*)&g_qn[(size_t)(m0 + r) * DDIM + k0 + lc];
            As[lc + 0][r] = va.x; As[lc + 1][r] = va.y;
            As[lc + 2][r] = va.z; As[lc + 3][r] = va.w;
            float4 vb = *(const float4*)&g_mn[(size_t)(n0 + r) * DDIM + k0 + lc];
            Bs[lc + 0][r] = vb.x; Bs[lc + 1][r] = vb.y;
            Bs[lc + 2][r] = vb.z; Bs[lc + 3][r] = vb.w;
        }
        __syncthreads();

        #pragma unroll
        for (int kk = 0; kk < BK; kk++) {
            #pragma unroll
            for (int i = 0; i < TM; i++) ar[i] = As[kk][ty * TM + i];
            #pragma unroll
            for (int j = 0; j < TN; j++) br[j] = Bs[kk][tx * TN + j];
            #pragma unroll
            for (int i = 0; i < TM; i++)
                #pragma unroll
                for (int j = 0; j < TN; j++)
                    acc[i][j] = fmaf(ar[i], br[j], acc[i][j]);
        }
        __syncthreads();
    }

    #pragma unroll
    for (int i = 0; i < TM; i++) {
        size_t rowoff = (size_t)(m0 + ty * TM + i) * NPAD + n0 + tx * TN;
        #pragma unroll
        for (int j4 = 0; j4 < TN; j4 += 4) {
            float4 v = make_float4(acc[i][j4], acc[i][j4 + 1],
                                   acc[i][j4 + 2], acc[i][j4 + 3]);
            *(float4*)&g_scores[rowoff + j4] = v;
        }
    }
}

// ---------------- top-k (k=8) + gather, one block of 256 per query ---------
__global__ void topk_kernel(const float* __restrict__ mem_raw,
                            float* __restrict__ out, int B) {
    const int q   = blockIdx.x;
    const int tid = threadIdx.x;
    const float* row = &g_scores[(size_t)q * NPAD];

    // per-thread top-8, ascending (v[0] = min)
    float v[KTOP]; int id[KTOP];
    #pragma unroll
    for (int i = 0; i < KTOP; i++) { v[i] = -1e30f; id[i] = 0x7fffffff; }

    for (int n = tid; n < NMEM; n += 256) {
        float s = row[n];
        if (s > v[0]) {
            int p = 0;
            #pragma unroll
            for (int i = 0; i < KTOP - 1; i++) {
                if (s > v[i + 1]) { v[i] = v[i + 1]; id[i] = id[i + 1]; p = i + 1; }
            }
            v[p] = s; id[p] = n;
        }
    }

    __shared__ float sv[256 * KTOP];
    __shared__ int   si[256 * KTOP];
    __shared__ float rv[256];
    __shared__ int   ri[256];
    __shared__ float top_val[KTOP];
    __shared__ int   top_idx[KTOP];

    #pragma unroll
    for (int i = 0; i < KTOP; i++) { sv[tid * KTOP + i] = v[i]; si[tid * KTOP + i] = id[i]; }

    for (int t = 0; t < KTOP; t++) {
        __syncthreads();
        // local argmax over this thread's 8 slots (tie -> lower memory index)
        int   bs = tid * KTOP;
        float bv = sv[bs];
        #pragma unroll
        for (int i = 1; i < KTOP; i++) {
            int   sl = tid * KTOP + i;
            float x  = sv[sl];
            if (x > bv || (x == bv && si[sl] < si[bs])) { bv = x; bs = sl; }
        }
        rv[tid] = bv; ri[tid] = bs;
        __syncthreads();
        for (int off = 128; off > 0; off >>= 1) {
            if (tid < off) {
                float a = rv[tid], b = rv[tid + off];
                if (b > a || (b == a && si[ri[tid + off]] < si[ri[tid]])) {
                    rv[tid] = b; ri[tid] = ri[tid + off];
                }
            }
            __syncthreads();
        }
        if (tid == 0) {
            int slot   = ri[0];
            top_val[t] = rv[0];
            top_idx[t] = si[slot];
            sv[slot]   = -1e38f;   // remove winner
        }
    }
    __syncthreads();

    // gather raw (un-normalized) memory rows: warp w copies row top_idx[w]
    int w = tid >> 5, lane = tid & 31;
    const float4* src = (const float4*)&mem_raw[(size_t)top_idx[w] * DDIM];
    float4* dst = (float4*)&out[((size_t)q * KTOP + w) * DDIM];
    dst[lane]      = src[lane];
    dst[lane + 32] = src[lane + 32];

    // scores after retrieved block
    if (tid < KTOP)
        out[(size_t)B * KTOP * DDIM + (size_t)q * KTOP + tid] = top_val[tid];
}

// ---------------- entry -----------------------------------------------------
extern "C" void kernel_launch(void* const* d_in, const int* in_sizes, int n_in,
                              void* d_out, int out_size) {
    const float* query = (const float*)d_in[0];
    const float* mem   = (const float*)d_in[1];
    float* out         = (float*)d_out;

    const int B = in_sizes[0] / DDIM;   // 2048
    const int N = in_sizes[1] / DDIM;   // 100000
    const int Npad = (N + 127) & ~127;  // 100096
    (void)n_in; (void)out_size; (void)Npad;

    // 1. normalize (warp per row)
    norm_query_kernel<<<(B * 32 + 255) / 256, 256>>>(query, B);
    norm_mem_kernel<<<(NPAD * 32 + 255) / 256, 256>>>(mem, N, NPAD);

    // 2. scores GEMM (x = 16 query tiles innermost -> B-tile L2 reuse)
    dim3 grid(B / BM, NPAD / BN);
    gemm_kernel<<<grid, 256>>>();

    // 3. top-8 + gather
    topk_kernel<<<B, 256>>>(mem, out, B);
}

// round 4
// speedup vs baseline: 2.3537x; 2.3537x over previous
#include <cuda_runtime.h>
#include <cuda_bf16.h>
#include <math.h>
#include <stdint.h>

// ---------------- problem constants ----------------------------------------
#define DDIM   256
#define KTOP   8
#define QT     128          // queries per CTA (M)
#define NT     128          // memory rows per tile (N)
#define BK     64           // K per mainloop step (64 bf16 = 128B smem rows)
#define KITERS (DDIM / BK)  // 4
#define NSPLIT 37           // 16 x 37 = 592 CTAs = 4 waves of 148
#define CTOP   16           // merged candidates re-ranked in fp32
#define NPAD_MAX 100096
#define BQ_MAX   2048

// ---------------- device scratch (static, no dynamic alloc) ----------------
__device__ __nv_bfloat16 g_qe[(size_t)BQ_MAX   * DDIM];  // normalized queries (1 MB)
__device__ __nv_bfloat16 g_me[(size_t)NPAD_MAX * DDIM];  // normalized memory (51 MB)
__device__ float g_cand_val[(size_t)BQ_MAX * NSPLIT * KTOP];
__device__ int   g_cand_idx[(size_t)BQ_MAX * NSPLIT * KTOP];

// ---------------- PTX helpers (plain-target instructions only) -------------
__device__ __forceinline__ uint32_t smem_to_u32(const void* p) {
    uint32_t a;
    asm("{ .reg .u64 t; cvta.to.shared.u64 t, %1; cvt.u32.u64 %0, t; }"
        : "=r"(a) : "l"(p));
    return a;
}

#define CP_ASYNC16(s, g) \
    asm volatile("cp.async.cg.shared.global [%0], [%1], 16;" :: "r"(s), "l"(g))
#define CP_COMMIT() asm volatile("cp.async.commit_group;" ::: "memory")
#define CP_WAIT(n)  asm volatile("cp.async.wait_group %0;" :: "n"(n) : "memory")

__device__ __forceinline__ void ldsm4(uint32_t* r, uint32_t a) {
    asm volatile("ldmatrix.sync.aligned.m8n8.x4.shared.b16 {%0,%1,%2,%3}, [%4];"
        : "=r"(r[0]), "=r"(r[1]), "=r"(r[2]), "=r"(r[3]) : "r"(a));
}

__device__ __forceinline__ void mma16816(float* d, const uint32_t* a,
                                         uint32_t b0, uint32_t b1) {
    asm volatile(
        "mma.sync.aligned.m16n8k16.row.col.f32.bf16.bf16.f32 "
        "{%0,%1,%2,%3}, {%4,%5,%6,%7}, {%8,%9}, {%0,%1,%2,%3};"
        : "+f"(d[0]), "+f"(d[1]), "+f"(d[2]), "+f"(d[3])
        : "r"(a[0]), "r"(a[1]), "r"(a[2]), "r"(a[3]), "r"(b0), "r"(b1));
}

// ---------------- normalize -> bf16 ----------------------------------------
__device__ __forceinline__ void norm_row_bf16(const float* __restrict__ in,
                                              __nv_bfloat16* __restrict__ out,
                                              int row, int lane) {
    const float4* src = (const float4*)(in + (size_t)row * DDIM);
    __nv_bfloat16* dst = out + (size_t)row * DDIM;
    float4 a = src[lane];
    float4 b = src[lane + 32];
    float ss = a.x*a.x + a.y*a.y + a.z*a.z + a.w*a.w
             + b.x*b.x + b.y*b.y + b.z*b.z + b.w*b.w;
    #pragma unroll
    for (int o = 16; o > 0; o >>= 1) ss += __shfl_xor_sync(0xffffffffu, ss, o);
    float inv = 1.0f / fmaxf(sqrtf(ss), 1e-12f);
    __nv_bfloat162 p0, p1, p2, p3;
    p0.x = __float2bfloat16(a.x * inv); p0.y = __float2bfloat16(a.y * inv);
    p1.x = __float2bfloat16(a.z * inv); p1.y = __float2bfloat16(a.w * inv);
    p2.x = __float2bfloat16(b.x * inv); p2.y = __float2bfloat16(b.y * inv);
    p3.x = __float2bfloat16(b.z * inv); p3.y = __float2bfloat16(b.w * inv);
    int k0 = 4 * lane;
    *(__nv_bfloat162*)(dst + k0)           = p0;
    *(__nv_bfloat162*)(dst + k0 + 2)       = p1;
    *(__nv_bfloat162*)(dst + 128 + k0)     = p2;
    *(__nv_bfloat162*)(dst + 128 + k0 + 2) = p3;
}

__global__ void norm_query_kernel(const float* __restrict__ q, int rows) {
    int warp = (blockIdx.x * blockDim.x + threadIdx.x) >> 5;
    int lane = threadIdx.x & 31;
    if (warp >= rows) return;
    norm_row_bf16(q, g_qe, warp, lane);
}

__global__ void norm_mem_kernel(const float* __restrict__ m, int rows_valid, int rows_total) {
    int warp = (blockIdx.x * blockDim.x + threadIdx.x) >> 5;
    int lane = threadIdx.x & 31;
    if (warp >= rows_total) return;
    if (warp >= rows_valid) {   // zero pad rows (score 0, never in top-8)
        float4* dst = (float4*)(g_me + (size_t)warp * DDIM);
        dst[lane] = make_float4(0.f, 0.f, 0.f, 0.f);
        return;
    }
    norm_row_bf16(m, g_me, warp, lane);
}

// ---------------- top-8 insertion (ascending, v[0]=min) --------------------
__device__ __forceinline__ void ins8(float s, int n, float v[KTOP], int id[KTOP]) {
    #pragma unroll
    for (int i = 0; i < KTOP; ++i) {
        if (s > v[i]) {
            bool up = (i < KTOP - 1) && (s > v[i + 1]);
            float nv = up ? v[i + 1] : s;
            int   ni = up ? id[i + 1] : n;
            v[i] = nv; id[i] = ni;
        }
    }
}

// ---------------- fused HMMA GEMM (bf16 filter) + per-split top-8 ----------
// smem: A resident (4 blocks x 16KB), B double buffer 2x16KB, staging 128x130 f32
#define SA    0
#define SB0   65536
#define SB1   81920
#define SSTG  98304
#define SSTR  130
#define SMEM_BYTES (SSTG + 128 * SSTR * 4)   // 164864

// load one 128-row x 64-col bf16 tile (gmem row stride 512B) with xor-swizzle
__device__ __forceinline__ void load_btile(uint32_t sbuf, const __nv_bfloat16* g, int tid) {
    #pragma unroll
    for (int j = 0; j < 4; ++j) {
        int c  = tid * 4 + j;            // 1024 16B chunks
        int m  = c >> 3;                 // row
        int cc = c & 7;                  // 16B chunk within row
        uint32_t sa = sbuf + (uint32_t)(m * 128 + ((cc ^ (m & 7)) << 4));
        CP_ASYNC16(sa, (const char*)g + (size_t)m * (DDIM * 2) + cc * 16);
    }
}

__global__ __launch_bounds__(256, 1)
void gemm_topk_kernel(int ntiles, int nmem) {
    extern __shared__ __align__(16) char smem[];
    const uint32_t sb = smem_to_u32(smem);
    const int tid  = threadIdx.x, lane = tid & 31, wid = tid >> 5;
    const int wm   = wid >> 1, wn = wid & 1;            // 4 x 2 warp grid
    const int m0   = blockIdx.x * QT, split = blockIdx.y;
    const int t0   = (split * ntiles) / NSPLIT;
    const int t1   = ((split + 1) * ntiles) / NSPLIT;

    // ldmatrix row/swizzle bases
    const int rA = wm * 32 + (lane & 15);
    const int rB = wn * 64 + (lane & 15);
    const int ch = lane >> 4;            // chunk-half selector for x4
    const int xA = rA & 7, xB = rB & 7;

    float v[KTOP]; int id[KTOP];
    #pragma unroll
    for (int i = 0; i < KTOP; ++i) { v[i] = -3e38f; id[i] = 0x7fffffff; }

    const __nv_bfloat16* gA = g_qe + (size_t)m0 * DDIM;
    const __nv_bfloat16* gB = g_me + (size_t)t0 * NT * DDIM;

    // prologue: resident A (4 K-blocks) + first B block
    #pragma unroll
    for (int kb = 0; kb < KITERS; ++kb)
        load_btile(sb + SA + kb * 16384, gA + kb * BK, tid);
    load_btile(sb + SB0, gB, tid);
    CP_COMMIT();

    float* stg = (float*)(smem + SSTG);

    for (int t = t0; t < t1; ++t) {
        const __nv_bfloat16* gBn = g_me + (size_t)(t + 1) * NT * DDIM;
        float acc[2][8][4];
        #pragma unroll
        for (int mi = 0; mi < 2; ++mi)
            #pragma unroll
            for (int nj = 0; nj < 8; ++nj)
                #pragma unroll
                for (int e = 0; e < 4; ++e) acc[mi][nj][e] = 0.f;

        #pragma unroll
        for (int kk = 0; kk < KITERS; ++kk) {
            const int p = kk & 1;
            CP_WAIT(0);
            __syncthreads();
            // issue next B into the other buffer (overlaps compute/epilogue)
            if (kk + 1 < KITERS)      load_btile(sb + (p ? SB0 : SB1), gB + (kk + 1) * BK, tid);
            else if (t + 1 < t1)      load_btile(sb + (p ? SB0 : SB1), gBn, tid);
            CP_COMMIT();

            const uint32_t bufA = sb + SA + (uint32_t)(kk * 16384);
            const uint32_t bufB = sb + (p ? SB1 : SB0);
            #pragma unroll
            for (int ks = 0; ks < 4; ++ks) {
                const int c = ks * 2 + ch;
                uint32_t a0[4], a1[4], bfr[4][4];
                const uint32_t swA = (uint32_t)((c ^ xA) << 4);
                ldsm4(a0, bufA + (uint32_t)(rA * 128) + swA);
                ldsm4(a1, bufA + (uint32_t)((rA + 16) * 128) + swA);
                const uint32_t swB = (uint32_t)((c ^ xB) << 4);
                #pragma unroll
                for (int g = 0; g < 4; ++g)
                    ldsm4(bfr[g], bufB + (uint32_t)((rB + g * 16) * 128) + swB);
                #pragma unroll
                for (int g = 0; g < 4; ++g) {
                    mma16816(acc[0][2*g],     a0, bfr[g][0], bfr[g][2]);
                    mma16816(acc[0][2*g + 1], a0, bfr[g][1], bfr[g][3]);
                    mma16816(acc[1][2*g],     a1, bfr[g][0], bfr[g][2]);
                    mma16816(acc[1][2*g + 1], a1, bfr[g][1], bfr[g][3]);
                }
            }
        }
        __syncthreads();

        // ---- epilogue: fragments -> smem staging -> per-row top-8 ----------
        const int er = wm * 32 + (lane >> 2);
        const int ec = wn * 64 + ((lane & 3) << 1);
        #pragma unroll
        for (int mi = 0; mi < 2; ++mi)
            #pragma unroll
            for (int nj = 0; nj < 8; ++nj) {
                int r1 = er + mi * 16, cc = ec + nj * 8;
                *(float2*)&stg[r1 * SSTR + cc]       = make_float2(acc[mi][nj][0], acc[mi][nj][1]);
                *(float2*)&stg[(r1 + 8) * SSTR + cc] = make_float2(acc[mi][nj][2], acc[mi][nj][3]);
            }
        __syncthreads();
        {
            const int qr = tid & 127, hf = tid >> 7;
            const float2* rp = (const float2*)&stg[qr * SSTR + hf * 64];
            const int nb = t * NT + hf * 64;
            #pragma unroll 8
            for (int jj = 0; jj < 32; ++jj) {
                float2 s2 = rp[jj];
                int n = nb + 2 * jj;
                if (s2.x > v[0] && n     < nmem) ins8(s2.x, n,     v, id);
                if (s2.y > v[0] && n + 1 < nmem) ins8(s2.y, n + 1, v, id);
            }
        }
        __syncthreads();
        gB = gBn;
    }

    // ---- merge the two half-row top-8 sets, write split candidates --------
    {
        const int qr = tid & 127, hf = tid >> 7;
        float* exv = stg;
        int*   exi = (int*)(stg + 128 * KTOP);
        if (hf == 1) {
            #pragma unroll
            for (int i = 0; i < KTOP; ++i) { exv[qr * KTOP + i] = v[i]; exi[qr * KTOP + i] = id[i]; }
        }
        __syncthreads();
        if (hf == 0) {
            #pragma unroll
            for (int i = 0; i < KTOP; ++i) {
                float s = exv[qr * KTOP + i]; int n = exi[qr * KTOP + i];
                if (s > v[0]) ins8(s, n, v, id);
            }
            const size_t base = ((size_t)(m0 + qr) * NSPLIT + split) * KTOP;
            #pragma unroll
            for (int i = 0; i < KTOP; ++i) {
                g_cand_val[base + i] = v[i];
                g_cand_idx[base + i] = id[i];
            }
        }
    }
}

// ---------------- merged top-16 + exact fp32 re-rank + gather --------------
// one warp per query; 8 warps per block
#define CSLOT 10    // ceil(296/32)

__global__ void rerank_kernel(const float* __restrict__ q,
                              const float* __restrict__ mem,
                              float* __restrict__ out, int B, int N) {
    const int lane = threadIdx.x & 31;
    const int qi   = blockIdx.x * 8 + (threadIdx.x >> 5);
    if (qi >= B) return;
    const int C = NSPLIT * KTOP;

    // load candidate (val, idx) pairs into registers
    float cv[CSLOT]; int ci[CSLOT];
    const size_t cb = (size_t)qi * C;
    #pragma unroll
    for (int j = 0; j < CSLOT; ++j) {
        int c = lane + j * 32;
        bool ok = c < C;
        cv[j] = ok ? g_cand_val[cb + c] : -3e38f;
        ci[j] = ok ? g_cand_idx[cb + c] : 0x7fffffff;
    }

    // normalized query in registers (mimic reference: divide by max(norm, eps))
    const float4* q4 = (const float4*)(q + (size_t)qi * DDIM);
    float4 qa = q4[lane], qb = q4[lane + 32];
    float qs = qa.x*qa.x + qa.y*qa.y + qa.z*qa.z + qa.w*qa.w
             + qb.x*qb.x + qb.y*qb.y + qb.z*qb.z + qb.w*qb.w;
    #pragma unroll
    for (int o = 16; o > 0; o >>= 1) qs += __shfl_xor_sync(0xffffffffu, qs, o);
    float qn = fmaxf(sqrtf(qs), 1e-12f);
    qa.x /= qn; qa.y /= qn; qa.z /= qn; qa.w /= qn;
    qb.x /= qn; qb.y /= qn; qb.z /= qn; qb.w /= qn;

    // final ordered top-8 (descending), tie -> lower index
    float sv[KTOP]; int si[KTOP];
    #pragma unroll
    for (int i = 0; i < KTOP; ++i) { sv[i] = -3e38f; si[i] = 0x7fffffff; }

    for (int r = 0; r < CTOP; ++r) {
        // warp argmax over remaining candidates (bf16 scores)
        float lv = cv[0]; int li = ci[0]; int ls = 0;
        #pragma unroll
        for (int j = 1; j < CSLOT; ++j)
            if (cv[j] > lv || (cv[j] == lv && ci[j] < li)) { lv = cv[j]; li = ci[j]; ls = j; }
        float bv = lv; int bi = li;
        #pragma unroll
        for (int o = 16; o > 0; o >>= 1) {
            float ov = __shfl_xor_sync(0xffffffffu, bv, o);
            int   oi = __shfl_xor_sync(0xffffffffu, bi, o);
            if (ov > bv || (ov == bv && oi < bi)) { bv = ov; bi = oi; }
        }
        if (lv == bv && li == bi) cv[ls] = -3e38f;   // unique owner clears
        const int n = bi;
        if (n < 0 || n >= N) continue;

        // exact fp32 re-score: normalize row then dot (reference op order)
        const float4* m4 = (const float4*)(mem + (size_t)n * DDIM);
        float4 ma = m4[lane], mb = m4[lane + 32];
        float ms = ma.x*ma.x + ma.y*ma.y + ma.z*ma.z + ma.w*ma.w
                 + mb.x*mb.x + mb.y*mb.y + mb.z*mb.z + mb.w*mb.w;
        #pragma unroll
        for (int o = 16; o > 0; o >>= 1) ms += __shfl_xor_sync(0xffffffffu, ms, o);
        float mn = fmaxf(sqrtf(ms), 1e-12f);
        float d = qa.x*(ma.x/mn) + qa.y*(ma.y/mn) + qa.z*(ma.z/mn) + qa.w*(ma.w/mn)
                + qb.x*(mb.x/mn) + qb.y*(mb.y/mn) + qb.z*(mb.z/mn) + qb.w*(mb.w/mn);
        #pragma unroll
        for (int o = 16; o > 0; o >>= 1) d += __shfl_xor_sync(0xffffffffu, d, o);

        // warp-uniform descending insertion, tie -> lower index
        #pragma unroll
        for (int i = KTOP - 1; i >= 0; --i) {
            bool above = (d > sv[i]) || (d == sv[i] && n < si[i]);
            if (above) {
                if (i < KTOP - 1) { sv[i + 1] = sv[i]; si[i + 1] = si[i]; }
                sv[i] = d; si[i] = n;
            }
        }
    }

    // write scores + gather raw rows
    #pragma unroll
    for (int r = 0; r < KTOP; ++r) {
        if (lane == 0)
            out[(size_t)B * KTOP * DDIM + (size_t)qi * KTOP + r] = sv[r];
        int n = si[r];
        if (n >= 0 && n < N) {
            const float4* src = (const float4*)(mem + (size_t)n * DDIM);
            float4* dst = (float4*)(out + ((size_t)qi * KTOP + r) * DDIM);
            dst[lane]      = src[lane];
            dst[lane + 32] = src[lane + 32];
        }
    }
}

// ---------------- entry -----------------------------------------------------
extern "C" void kernel_launch(void* const* d_in, const int* in_sizes, int n_in,
                              void* d_out, int out_size) {
    const float* query = (const float*)d_in[0];
    const float* mem   = (const float*)d_in[1];
    float* out         = (float*)d_out;
    (void)n_in; (void)out_size;

    const int B = in_sizes[0] / DDIM;            // 2048
    const int N = in_sizes[1] / DDIM;            // 100000
    const int ntiles = (N + NT - 1) / NT;        // 782
    const int nrows_pad = ntiles * NT;           // 100096

    norm_query_kernel<<<(B * 32 + 255) / 256, 256>>>(query, B);
    norm_mem_kernel<<<(nrows_pad * 32 + 255) / 256, 256>>>(mem, N, nrows_pad);

    cudaFuncSetAttribute(gemm_topk_kernel,
                         cudaFuncAttributeMaxDynamicSharedMemorySize, SMEM_BYTES);
    dim3 grid(B / QT, NSPLIT);
    gemm_topk_kernel<<<grid, 256, SMEM_BYTES>>>(ntiles, N);

    rerank_kernel<<<(B + 7) / 8, 256>>>(query, mem, out, B, N);
}

// round 5
// speedup vs baseline: 3.4491x; 1.4654x over previous
#include <cuda_runtime.h>
#include <cuda_bf16.h>
#include <cuda_fp8.h>
#include <math.h>
#include <stdint.h>

// ---------------- problem constants ----------------------------------------
#define DDIM   256
#define KTOP   8
#define SPK    16           // per-split candidate list size
#define CTOP   32           // merged candidates re-ranked exactly in fp32
#define QT     128          // queries per CTA (M)
#define NT     128          // memory rows per tile (N)
#define NSPLIT 18           // 16 x 18 = 288 CTAs = 2 waves of 148
#define NPAD_MAX 100096
#define BQ_MAX   2048

// ---------------- device scratch (static, no dynamic alloc) ----------------
__device__ uint8_t g_qe[(size_t)BQ_MAX   * DDIM];   // normalized queries, e4m3 x16
__device__ uint8_t g_me[(size_t)NPAD_MAX * DDIM];   // normalized memory,  e4m3 x16 (25.6MB)
__device__ float g_cand_val[(size_t)BQ_MAX * NSPLIT * SPK];
__device__ int   g_cand_idx[(size_t)BQ_MAX * NSPLIT * SPK];

// ---------------- PTX helpers (plain-target instructions only) -------------
__device__ __forceinline__ uint32_t smem_to_u32(const void* p) {
    uint32_t a;
    asm("{ .reg .u64 t; cvta.to.shared.u64 t, %1; cvt.u32.u64 %0, t; }"
        : "=r"(a) : "l"(p));
    return a;
}

#define CP_ASYNC16(s, g) \
    asm volatile("cp.async.cg.shared.global [%0], [%1], 16;" :: "r"(s), "l"(g))
#define CP_COMMIT() asm volatile("cp.async.commit_group;" ::: "memory")
#define CP_WAIT(n)  asm volatile("cp.async.wait_group %0;" :: "n"(n) : "memory")

__device__ __forceinline__ void ldsm4(uint32_t* r, uint32_t a) {
    asm volatile("ldmatrix.sync.aligned.m8n8.x4.shared.b16 {%0,%1,%2,%3}, [%4];"
        : "=r"(r[0]), "=r"(r[1]), "=r"(r[2]), "=r"(r[3]) : "r"(a));
}

// fp8 e4m3 MMA: D(16x8,f32) += A(16x32) * B(32x8)
__device__ __forceinline__ void mma16832(float* d, const uint32_t* a,
                                         uint32_t b0, uint32_t b1) {
    asm volatile(
        "mma.sync.aligned.m16n8k32.row.col.f32.e4m3.e4m3.f32 "
        "{%0,%1,%2,%3}, {%4,%5,%6,%7}, {%8,%9}, {%0,%1,%2,%3};"
        : "+f"(d[0]), "+f"(d[1]), "+f"(d[2]), "+f"(d[3])
        : "r"(a[0]), "r"(a[1]), "r"(a[2]), "r"(a[3]), "r"(b0), "r"(b1));
}

// ---------------- normalize -> e4m3 (scaled by 16) -------------------------
__device__ __forceinline__ uint32_t pack_e4m3x4(float x, float y, float z, float w) {
    __nv_fp8x4_e4m3 p(make_float4(x, y, z, w));
    return *reinterpret_cast<uint32_t*>(&p);
}

__device__ __forceinline__ void norm_row_fp8(const float* __restrict__ in,
                                             uint8_t* __restrict__ out,
                                             int row, int lane) {
    const float4* src = (const float4*)(in + (size_t)row * DDIM);
    uint32_t* dst = (uint32_t*)(out + (size_t)row * DDIM);
    float4 a = src[lane];
    float4 b = src[lane + 32];
    float ss = a.x*a.x + a.y*a.y + a.z*a.z + a.w*a.w
             + b.x*b.x + b.y*b.y + b.z*b.z + b.w*b.w;
    #pragma unroll
    for (int o = 16; o > 0; o >>= 1) ss += __shfl_xor_sync(0xffffffffu, ss, o);
    float inv = 16.0f / fmaxf(sqrtf(ss), 1e-12f);   // x16: center into e4m3 sweet spot
    dst[lane]      = pack_e4m3x4(a.x*inv, a.y*inv, a.z*inv, a.w*inv);
    dst[lane + 32] = pack_e4m3x4(b.x*inv, b.y*inv, b.z*inv, b.w*inv);
}

__global__ void norm_query_kernel(const float* __restrict__ q, int rows) {
    int warp = (blockIdx.x * blockDim.x + threadIdx.x) >> 5;
    int lane = threadIdx.x & 31;
    if (warp >= rows) return;
    norm_row_fp8(q, g_qe, warp, lane);
}

__global__ void norm_mem_kernel(const float* __restrict__ m, int rows_valid, int rows_total) {
    int warp = (blockIdx.x * blockDim.x + threadIdx.x) >> 5;
    int lane = threadIdx.x & 31;
    if (warp >= rows_total) return;
    if (warp >= rows_valid) {   // zero pad rows (score 0, never candidate)
        uint32_t* dst = (uint32_t*)(g_me + (size_t)warp * DDIM);
        dst[lane] = 0u; dst[lane + 32] = 0u;
        return;
    }
    norm_row_fp8(m, g_me, warp, lane);
}

// ---------------- top-L insertion (ascending, v[0]=min) --------------------
template <int L>
__device__ __forceinline__ void insL(float s, int n, float* v, int* id) {
    #pragma unroll
    for (int i = 0; i < L; ++i) {
        if (s > v[i]) {
            bool up = (i < L - 1) && (s > v[i + 1]);
            float nv = up ? v[i + 1] : s;
            int   ni = up ? id[i + 1] : n;
            v[i] = nv; id[i] = ni;
        }
    }
}

// ---------------- fused fp8 QMMA GEMM (filter) + per-split top-16 ----------
// smem: A resident 32KB, B double buffer 2x32KB, fp32 staging 128x130
#define SA    0
#define SB0   32768
#define SB1   65536
#define SSTG  98304
#define SSTR  130
#define SMEM_BYTES (SSTG + 128 * SSTR * 4)   // 164864

// load one 128-row x 256-byte fp8 tile with xor-swizzle (16B granules)
__device__ __forceinline__ void load_tile8(uint32_t sbuf, const uint8_t* g, int tid) {
    #pragma unroll
    for (int j = 0; j < 8; ++j) {
        int c_lin = j * 256 + tid;          // 2048 16B chunks
        int row = c_lin >> 4;
        int c   = c_lin & 15;
        uint32_t sw = (uint32_t)(((c ^ row) & 7) | (c & 8));
        CP_ASYNC16(sbuf + (uint32_t)(row * 256) + (sw << 4),
                   g + (size_t)row * 256 + c * 16);
    }
}

__global__ __launch_bounds__(256, 1)
void gemm_topk_kernel(int ntiles, int nmem) {
    extern __shared__ __align__(16) char smem[];
    const uint32_t sb = smem_to_u32(smem);
    const int tid  = threadIdx.x, lane = tid & 31, wid = tid >> 5;
    const int wm   = wid >> 1, wn = wid & 1;            // 4 x 2 warp grid
    const int m0   = blockIdx.x * QT, split = blockIdx.y;
    const int t0   = (split * ntiles) / NSPLIT;
    const int t1   = ((split + 1) * ntiles) / NSPLIT;

    // ldmatrix row bases (16B-granule swizzle keyed on row&7)
    const int rA = wm * 32 + (lane & 15);
    const int rB = wn * 64 + (lane & 15);
    const int ch = lane >> 4;            // 16B half of each 32B k-step
    const int xA = rA & 7, xB = rB & 7;

    float v[SPK]; int id[SPK];
    #pragma unroll
    for (int i = 0; i < SPK; ++i) { v[i] = -3e38f; id[i] = 0x7fffffff; }

    const uint8_t* gA = g_qe + (size_t)m0 * DDIM;

    // prologue: resident A (whole K) + first B tile
    load_tile8(sb + SA, gA, tid);
    load_tile8(sb + SB0, g_me + (size_t)t0 * NT * DDIM, tid);
    CP_COMMIT();

    float* stg = (float*)(smem + SSTG);

    for (int t = t0; t < t1; ++t) {
        const int p = (t - t0) & 1;
        const uint32_t bufB = sb + (p ? SB1 : SB0);

        CP_WAIT(0);
        __syncthreads();
        if (t + 1 < t1) {   // prefetch next B tile into other buffer
            load_tile8(sb + (p ? SB0 : SB1), g_me + (size_t)(t + 1) * NT * DDIM, tid);
            CP_COMMIT();
        }

        float acc[2][8][4];
        #pragma unroll
        for (int mi = 0; mi < 2; ++mi)
            #pragma unroll
            for (int nj = 0; nj < 8; ++nj)
                #pragma unroll
                for (int e = 0; e < 4; ++e) acc[mi][nj][e] = 0.f;

        const uint32_t bufA = sb + SA;
        #pragma unroll
        for (int ks = 0; ks < 8; ++ks) {
            const int c = ks * 2 + ch;
            const uint32_t swA = (uint32_t)((((c ^ xA) & 7) | (c & 8)) << 4);
            const uint32_t swB = (uint32_t)((((c ^ xB) & 7) | (c & 8)) << 4);
            uint32_t a0[4], a1[4], bfr[4][4];
            ldsm4(a0, bufA + (uint32_t)(rA * 256) + swA);
            ldsm4(a1, bufA + (uint32_t)((rA + 16) * 256) + swA);
            #pragma unroll
            for (int g = 0; g < 4; ++g)
                ldsm4(bfr[g], bufB + (uint32_t)((rB + g * 16) * 256) + swB);
            #pragma unroll
            for (int g = 0; g < 4; ++g) {
                mma16832(acc[0][2*g],     a0, bfr[g][0], bfr[g][2]);
                mma16832(acc[0][2*g + 1], a0, bfr[g][1], bfr[g][3]);
                mma16832(acc[1][2*g],     a1, bfr[g][0], bfr[g][2]);
                mma16832(acc[1][2*g + 1], a1, bfr[g][1], bfr[g][3]);
            }
        }
        __syncthreads();

        // ---- epilogue: fragments -> smem staging -> per-half-row top-16 ----
        const int er = wm * 32 + (lane >> 2);
        const int ec = wn * 64 + ((lane & 3) << 1);
        #pragma unroll
        for (int mi = 0; mi < 2; ++mi)
            #pragma unroll
            for (int nj = 0; nj < 8; ++nj) {
                int r1 = er + mi * 16, cc = ec + nj * 8;
                *(float2*)&stg[r1 * SSTR + cc]       = make_float2(acc[mi][nj][0], acc[mi][nj][1]);
                *(float2*)&stg[(r1 + 8) * SSTR + cc] = make_float2(acc[mi][nj][2], acc[mi][nj][3]);
            }
        __syncthreads();
        {
            const int qr = tid & 127, hf = tid >> 7;
            const float2* rp = (const float2*)&stg[qr * SSTR + hf * 64];
            const int nb = t * NT + hf * 64;
            #pragma unroll 8
            for (int jj = 0; jj < 32; ++jj) {
                float2 s2 = rp[jj];
                int n = nb + 2 * jj;
                if (s2.x > v[0] && n     < nmem) insL<SPK>(s2.x, n,     v, id);
                if (s2.y > v[0] && n + 1 < nmem) insL<SPK>(s2.y, n + 1, v, id);
            }
        }
        __syncthreads();
    }

    // ---- merge the two half-row top-16 sets, write split candidates -------
    {
        const int qr = tid & 127, hf = tid >> 7;
        float* exv = stg;
        int*   exi = (int*)(stg + 128 * SPK);
        if (hf == 1) {
            #pragma unroll
            for (int i = 0; i < SPK; ++i) { exv[qr * SPK + i] = v[i]; exi[qr * SPK + i] = id[i]; }
        }
        __syncthreads();
        if (hf == 0) {
            #pragma unroll
            for (int i = 0; i < SPK; ++i) {
                float s = exv[qr * SPK + i]; int n = exi[qr * SPK + i];
                if (s > v[0]) insL<SPK>(s, n, v, id);
            }
            const size_t base = ((size_t)(m0 + qr) * NSPLIT + split) * SPK;
            #pragma unroll
            for (int i = 0; i < SPK; ++i) {
                g_cand_val[base + i] = v[i];
                g_cand_idx[base + i] = id[i];
            }
        }
    }
}

// ---------------- merged top-32 + exact fp32 re-rank + gather --------------
// one warp per query; 8 warps per block
#define CANDN (NSPLIT * SPK)   // 288
#define CSLOT (CANDN / 32)     // 9

__global__ void rerank_kernel(const float* __restrict__ q,
                              const float* __restrict__ mem,
                              float* __restrict__ out, int B, int N) {
    const int lane = threadIdx.x & 31;
    const int qi   = blockIdx.x * 8 + (threadIdx.x >> 5);
    if (qi >= B) return;

    // candidate (val, idx) pairs in registers
    float cv[CSLOT]; int ci[CSLOT];
    const size_t cb = (size_t)qi * CANDN;
    #pragma unroll
    for (int j = 0; j < CSLOT; ++j) {
        int c = lane + j * 32;
        cv[j] = g_cand_val[cb + c];
        ci[j] = g_cand_idx[cb + c];
    }

    // normalized query in registers (reference op order: / max(norm, eps))
    const float4* q4 = (const float4*)(q + (size_t)qi * DDIM);
    float4 qa = q4[lane], qb = q4[lane + 32];
    float qs = qa.x*qa.x + qa.y*qa.y + qa.z*qa.z + qa.w*qa.w
             + qb.x*qb.x + qb.y*qb.y + qb.z*qb.z + qb.w*qb.w;
    #pragma unroll
    for (int o = 16; o > 0; o >>= 1) qs += __shfl_xor_sync(0xffffffffu, qs, o);
    float qn = fmaxf(sqrtf(qs), 1e-12f);
    qa.x /= qn; qa.y /= qn; qa.z /= qn; qa.w /= qn;
    qb.x /= qn; qb.y /= qn; qb.z /= qn; qb.w /= qn;

    // final ordered top-8 (descending), tie -> lower index
    float sv[KTOP]; int si[KTOP];
    #pragma unroll
    for (int i = 0; i < KTOP; ++i) { sv[i] = -3e38f; si[i] = 0x7fffffff; }

    for (int r = 0; r < CTOP; ++r) {
        // warp argmax over remaining candidates (filter scores)
        float lv = cv[0]; int li = ci[0]; int ls = 0;
        #pragma unroll
        for (int j = 1; j < CSLOT; ++j)
            if (cv[j] > lv || (cv[j] == lv && ci[j] < li)) { lv = cv[j]; li = ci[j]; ls = j; }
        float bv = lv; int bi = li;
        #pragma unroll
        for (int o = 16; o > 0; o >>= 1) {
            float ov = __shfl_xor_sync(0xffffffffu, bv, o);
            int   oi = __shfl_xor_sync(0xffffffffu, bi, o);
            if (ov > bv || (ov == bv && oi < bi)) { bv = ov; bi = oi; }
        }
        if (lv == bv && li == bi) cv[ls] = -3e38f;   // unique owner clears
        const int n = bi;
        if (n < 0 || n >= N) continue;

        // exact fp32 re-score (reference op order)
        const float4* m4 = (const float4*)(mem + (size_t)n * DDIM);
        float4 ma = m4[lane], mb = m4[lane + 32];
        float ms = ma.x*ma.x + ma.y*ma.y + ma.z*ma.z + ma.w*ma.w
                 + mb.x*mb.x + mb.y*mb.y + mb.z*mb.z + mb.w*mb.w;
        #pragma unroll
        for (int o = 16; o > 0; o >>= 1) ms += __shfl_xor_sync(0xffffffffu, ms, o);
        float mn = fmaxf(sqrtf(ms), 1e-12f);
        float d = qa.x*(ma.x/mn) + qa.y*(ma.y/mn) + qa.z*(ma.z/mn) + qa.w*(ma.w/mn)
                + qb.x*(mb.x/mn) + qb.y*(mb.y/mn) + qb.z*(mb.z/mn) + qb.w*(mb.w/mn);
        #pragma unroll
        for (int o = 16; o > 0; o >>= 1) d += __shfl_xor_sync(0xffffffffu, d, o);

        // warp-uniform descending insertion, tie -> lower index
        #pragma unroll
        for (int i = KTOP - 1; i >= 0; --i) {
            bool above = (d > sv[i]) || (d == sv[i] && n < si[i]);
            if (above) {
                if (i < KTOP - 1) { sv[i + 1] = sv[i]; si[i + 1] = si[i]; }
                sv[i] = d; si[i] = n;
            }
        }
    }

    // write scores + gather raw rows
    #pragma unroll
    for (int r = 0; r < KTOP; ++r) {
        if (lane == 0)
            out[(size_t)B * KTOP * DDIM + (size_t)qi * KTOP + r] = sv[r];
        int n = si[r];
        if (n >= 0 && n < N) {
            const float4* src = (const float4*)(mem + (size_t)n * DDIM);
            float4* dst = (float4*)(out + ((size_t)qi * KTOP + r) * DDIM);
            dst[lane]      = src[lane];
            dst[lane + 32] = src[lane + 32];
        }
    }
}

// ---------------- entry -----------------------------------------------------
extern "C" void kernel_launch(void* const* d_in, const int* in_sizes, int n_in,
                              void* d_out, int out_size) {
    const float* query = (const float*)d_in[0];
    const float* mem   = (const float*)d_in[1];
    float* out         = (float*)d_out;
    (void)n_in; (void)out_size;

    const int B = in_sizes[0] / DDIM;            // 2048
    const int N = in_sizes[1] / DDIM;            // 100000
    const int ntiles = (N + NT - 1) / NT;        // 782
    const int nrows_pad = ntiles * NT;           // 100096

    norm_query_kernel<<<(B * 32 + 255) / 256, 256>>>(query, B);
    norm_mem_kernel<<<(nrows_pad * 32 + 255) / 256, 256>>>(mem, N, nrows_pad);

    cudaFuncSetAttribute(gemm_topk_kernel,
                         cudaFuncAttributeMaxDynamicSharedMemorySize, SMEM_BYTES);
    dim3 grid(B / QT, NSPLIT);
    gemm_topk_kernel<<<grid, 256, SMEM_BYTES>>>(ntiles, N);

    rerank_kernel<<<(B + 7) / 8, 256>>>(query, mem, out, B, N);
}

// round 6
// speedup vs baseline: 5.8999x; 1.7105x over previous
#include <cuda_runtime.h>
#include <cuda_bf16.h>
#include <cuda_fp8.h>
#include <math.h>
#include <stdint.h>

// ---------------- problem constants ----------------------------------------
#define DDIM   256
#define KTOP   8
#define CDEP   4            // per-thread per-row candidate depth
#define CPS    32           // candidates per (query, split) = 8 threads x CDEP
#define CTOP   32           // merged candidates re-ranked exactly in fp32
#define QT     128          // queries per CTA (M)
#define NT     128          // memory rows per tile (N)
#define NSPLIT 18           // 16 x 18 = 288 CTAs; 2 CTA/SM -> 1 wave of 296
#define NPAD_MAX 100096
#define BQ_MAX   2048

// ---------------- device scratch (static, no dynamic alloc) ----------------
__device__ uint8_t g_qe[(size_t)BQ_MAX   * DDIM];   // normalized queries, e4m3 x16
__device__ uint8_t g_me[(size_t)NPAD_MAX * DDIM];   // normalized memory,  e4m3 x16
__device__ float g_cand_val[(size_t)BQ_MAX * NSPLIT * CPS];
__device__ int   g_cand_idx[(size_t)BQ_MAX * NSPLIT * CPS];

// ---------------- PTX helpers (plain-target instructions only) -------------
__device__ __forceinline__ uint32_t smem_to_u32(const void* p) {
    uint32_t a;
    asm("{ .reg .u64 t; cvta.to.shared.u64 t, %1; cvt.u32.u64 %0, t; }"
        : "=r"(a) : "l"(p));
    return a;
}

#define CP_ASYNC16(s, g) \
    asm volatile("cp.async.cg.shared.global [%0], [%1], 16;" :: "r"(s), "l"(g))
#define CP_COMMIT() asm volatile("cp.async.commit_group;" ::: "memory")
#define CP_WAIT(n)  asm volatile("cp.async.wait_group %0;" :: "n"(n) : "memory")

__device__ __forceinline__ void ldsm4(uint32_t* r, uint32_t a) {
    asm volatile("ldmatrix.sync.aligned.m8n8.x4.shared.b16 {%0,%1,%2,%3}, [%4];"
        : "=r"(r[0]), "=r"(r[1]), "=r"(r[2]), "=r"(r[3]) : "r"(a));
}

// fp8 e4m3 MMA: D(16x8,f32) += A(16x32) * B(32x8)
__device__ __forceinline__ void mma16832(float* d, const uint32_t* a,
                                         uint32_t b0, uint32_t b1) {
    asm volatile(
        "mma.sync.aligned.m16n8k32.row.col.f32.e4m3.e4m3.f32 "
        "{%0,%1,%2,%3}, {%4,%5,%6,%7}, {%8,%9}, {%0,%1,%2,%3};"
        : "+f"(d[0]), "+f"(d[1]), "+f"(d[2]), "+f"(d[3])
        : "r"(a[0]), "r"(a[1]), "r"(a[2]), "r"(a[3]), "r"(b0), "r"(b1));
}

// ---------------- normalize -> e4m3 (scaled by 16) -------------------------
__device__ __forceinline__ uint32_t pack_e4m3x4(float x, float y, float z, float w) {
    __nv_fp8x4_e4m3 p(make_float4(x, y, z, w));
    return *reinterpret_cast<uint32_t*>(&p);
}

__device__ __forceinline__ void norm_row_fp8(const float* __restrict__ in,
                                             uint8_t* __restrict__ out,
                                             int row, int lane) {
    const float4* src = (const float4*)(in + (size_t)row * DDIM);
    uint32_t* dst = (uint32_t*)(out + (size_t)row * DDIM);
    float4 a = src[lane];
    float4 b = src[lane + 32];
    float ss = a.x*a.x + a.y*a.y + a.z*a.z + a.w*a.w
             + b.x*b.x + b.y*b.y + b.z*b.z + b.w*b.w;
    #pragma unroll
    for (int o = 16; o > 0; o >>= 1) ss += __shfl_xor_sync(0xffffffffu, ss, o);
    float inv = 16.0f / fmaxf(sqrtf(ss), 1e-12f);   // x16 centers e4m3 range
    dst[lane]      = pack_e4m3x4(a.x*inv, a.y*inv, a.z*inv, a.w*inv);
    dst[lane + 32] = pack_e4m3x4(b.x*inv, b.y*inv, b.z*inv, b.w*inv);
}

__global__ void norm_query_kernel(const float* __restrict__ q, int rows) {
    int warp = (blockIdx.x * blockDim.x + threadIdx.x) >> 5;
    int lane = threadIdx.x & 31;
    if (warp >= rows) return;
    norm_row_fp8(q, g_qe, warp, lane);
}

__global__ void norm_mem_kernel(const float* __restrict__ m, int rows_valid, int rows_total) {
    int warp = (blockIdx.x * blockDim.x + threadIdx.x) >> 5;
    int lane = threadIdx.x & 31;
    if (warp >= rows_total) return;
    if (warp >= rows_valid) {   // zero pad rows (score 0; rerank drops idx >= N)
        uint32_t* dst = (uint32_t*)(g_me + (size_t)warp * DDIM);
        dst[lane] = 0u; dst[lane + 32] = 0u;
        return;
    }
    norm_row_fp8(m, g_me, warp, lane);
}

// ---------------- top-L insertion (ascending, v[0]=min) --------------------
template <int L>
__device__ __forceinline__ void insL(float s, int n, float* v, int* id) {
    #pragma unroll
    for (int i = 0; i < L; ++i) {
        if (s > v[i]) {
            bool up = (i < L - 1) && (s > v[i + 1]);
            float nv = up ? v[i + 1] : s;
            int   ni = up ? id[i + 1] : n;
            v[i] = nv; id[i] = ni;
        }
    }
}

// ---------------- fused fp8 QMMA GEMM + fragment-direct top-4 --------------
// smem: A resident 32KB + B double buffer 2x32KB  -> 2 CTAs/SM
#define SA    0
#define SB0   32768
#define SB1   65536
#define SMEM_BYTES 98304

// load one 128-row x 256-byte fp8 tile with xor-swizzle (16B granules)
__device__ __forceinline__ void load_tile8(uint32_t sbuf, const uint8_t* g, int tid) {
    #pragma unroll
    for (int j = 0; j < 8; ++j) {
        int c_lin = j * 256 + tid;          // 2048 16B chunks
        int row = c_lin >> 4;
        int c   = c_lin & 15;
        uint32_t sw = (uint32_t)(((c ^ row) & 7) | (c & 8));
        CP_ASYNC16(sbuf + (uint32_t)(row * 256) + (sw << 4),
                   g + (size_t)row * 256 + c * 16);
    }
}

__global__ __launch_bounds__(256, 2)
void gemm_topk_kernel(int ntiles) {
    extern __shared__ __align__(16) char smem[];
    const uint32_t sb = smem_to_u32(smem);
    const int tid  = threadIdx.x, lane = tid & 31, wid = tid >> 5;
    const int wm   = wid >> 1, wn = wid & 1;            // 4 x 2 warp grid
    const int m0   = blockIdx.x * QT, split = blockIdx.y;
    const int t0   = (split * ntiles) / NSPLIT;
    const int t1   = ((split + 1) * ntiles) / NSPLIT;

    // ldmatrix row bases (16B-granule swizzle keyed on row&7)
    const int rA = wm * 32 + (lane & 15);
    const int rB = wn * 64 + (lane & 15);
    const int ch = lane >> 4;            // 16B half of each 32B k-step
    const int xA = rA & 7, xB = rB & 7;

    // per-thread candidates: 4 owned query-rows x depth-4 (ascending)
    float cv[4][CDEP]; int ci[4][CDEP];
    #pragma unroll
    for (int r = 0; r < 4; ++r)
        #pragma unroll
        for (int i = 0; i < CDEP; ++i) { cv[r][i] = -3e38f; ci[r][i] = 0x7fffffff; }

    // prologue: resident A (whole K) + first B tile
    load_tile8(sb + SA, g_qe + (size_t)m0 * DDIM, tid);
    load_tile8(sb + SB0, g_me + (size_t)t0 * NT * DDIM, tid);
    CP_COMMIT();

    const int colbase = wn * 64 + ((lane & 3) << 1);   // fragment column base

    for (int t = t0; t < t1; ++t) {
        const int p = (t - t0) & 1;
        const uint32_t bufB = sb + (p ? SB1 : SB0);

        CP_WAIT(0);
        __syncthreads();
        if (t + 1 < t1) {   // prefetch next B tile into the other buffer
            load_tile8(sb + (p ? SB0 : SB1), g_me + (size_t)(t + 1) * NT * DDIM, tid);
            CP_COMMIT();
        }

        float acc[2][8][4];
        #pragma unroll
        for (int mi = 0; mi < 2; ++mi)
            #pragma unroll
            for (int nj = 0; nj < 8; ++nj)
                #pragma unroll
                for (int e = 0; e < 4; ++e) acc[mi][nj][e] = 0.f;

        const uint32_t bufA = sb + SA;
        #pragma unroll
        for (int ks = 0; ks < 8; ++ks) {
            const int c = ks * 2 + ch;
            const uint32_t swA = (uint32_t)((((c ^ xA) & 7) | (c & 8)) << 4);
            const uint32_t swB = (uint32_t)((((c ^ xB) & 7) | (c & 8)) << 4);
            uint32_t a0[4], a1[4], bfr[4][4];
            ldsm4(a0, bufA + (uint32_t)(rA * 256) + swA);
            ldsm4(a1, bufA + (uint32_t)((rA + 16) * 256) + swA);
            #pragma unroll
            for (int g = 0; g < 4; ++g)
                ldsm4(bfr[g], bufB + (uint32_t)((rB + g * 16) * 256) + swB);
            #pragma unroll
            for (int g = 0; g < 4; ++g) {
                mma16832(acc[0][2*g],     a0, bfr[g][0], bfr[g][2]);
                mma16832(acc[0][2*g + 1], a0, bfr[g][1], bfr[g][3]);
                mma16832(acc[1][2*g],     a1, bfr[g][0], bfr[g][2]);
                mma16832(acc[1][2*g + 1], a1, bfr[g][1], bfr[g][3]);
            }
        }

        // ---- fragment-direct scan: insert owned scores into top-4 lists ---
        const int nb = t * NT + colbase;
        #pragma unroll
        for (int mi = 0; mi < 2; ++mi)
            #pragma unroll
            for (int nj = 0; nj < 8; ++nj) {
                const int n0 = nb + nj * 8;
                float* a = acc[mi][nj];
                // rows list idx: 2*mi (e0,e1) and 2*mi+1 (e2,e3)
                if (a[0] > cv[2*mi][0])     insL<CDEP>(a[0], n0,     cv[2*mi],     ci[2*mi]);
                if (a[1] > cv[2*mi][0])     insL<CDEP>(a[1], n0 + 1, cv[2*mi],     ci[2*mi]);
                if (a[2] > cv[2*mi + 1][0]) insL<CDEP>(a[2], n0,     cv[2*mi + 1], ci[2*mi + 1]);
                if (a[3] > cv[2*mi + 1][0]) insL<CDEP>(a[3], n0 + 1, cv[2*mi + 1], ci[2*mi + 1]);
            }
    }

    // ---- write candidates: slot = wn*4 + (lane&3), 4 entries each ---------
    {
        const int er   = wm * 32 + (lane >> 2);
        const int slot = wn * 4 + (lane & 3);
        #pragma unroll
        for (int r = 0; r < 4; ++r) {
            const int qrow = m0 + er + (r >> 1) * 16 + (r & 1) * 8;
            const size_t base = ((size_t)qrow * NSPLIT + split) * CPS + slot * CDEP;
            #pragma unroll
            for (int i = 0; i < CDEP; ++i) {
                g_cand_val[base + i] = cv[r][i];
                g_cand_idx[base + i] = ci[r][i];
            }
        }
    }
}

// ---------------- merged top-32 + exact fp32 re-rank + gather --------------
// one warp per query; 8 warps per block
#define CANDN (NSPLIT * CPS)   // 576
#define CSLOT (CANDN / 32)     // 18

__global__ void rerank_kernel(const float* __restrict__ q,
                              const float* __restrict__ mem,
                              float* __restrict__ out, int B, int N) {
    const int lane = threadIdx.x & 31;
    const int qi   = blockIdx.x * 8 + (threadIdx.x >> 5);
    if (qi >= B) return;

    // candidate (val, idx) pairs in registers
    float cv[CSLOT]; int ci[CSLOT];
    const size_t cb = (size_t)qi * CANDN;
    #pragma unroll
    for (int j = 0; j < CSLOT; ++j) {
        int c = lane + j * 32;
        cv[j] = g_cand_val[cb + c];
        ci[j] = g_cand_idx[cb + c];
    }

    // normalized query in registers (reference op order: / max(norm, eps))
    const float4* q4 = (const float4*)(q + (size_t)qi * DDIM);
    float4 qa = q4[lane], qb = q4[lane + 32];
    float qs = qa.x*qa.x + qa.y*qa.y + qa.z*qa.z + qa.w*qa.w
             + qb.x*qb.x + qb.y*qb.y + qb.z*qb.z + qb.w*qb.w;
    #pragma unroll
    for (int o = 16; o > 0; o >>= 1) qs += __shfl_xor_sync(0xffffffffu, qs, o);
    float qn = fmaxf(sqrtf(qs), 1e-12f);
    qa.x /= qn; qa.y /= qn; qa.z /= qn; qa.w /= qn;
    qb.x /= qn; qb.y /= qn; qb.z /= qn; qb.w /= qn;

    // final ordered top-8 (descending), tie -> lower index
    float sv[KTOP]; int si[KTOP];
    #pragma unroll
    for (int i = 0; i < KTOP; ++i) { sv[i] = -3e38f; si[i] = 0x7fffffff; }

    for (int r = 0; r < CTOP; ++r) {
        // warp argmax over remaining candidates (filter scores)
        float lv = cv[0]; int li = ci[0]; int ls = 0;
        #pragma unroll
        for (int j = 1; j < CSLOT; ++j)
            if (cv[j] > lv || (cv[j] == lv && ci[j] < li)) { lv = cv[j]; li = ci[j]; ls = j; }
        float bv = lv; int bi = li;
        #pragma unroll
        for (int o = 16; o > 0; o >>= 1) {
            float ov = __shfl_xor_sync(0xffffffffu, bv, o);
            int   oi = __shfl_xor_sync(0xffffffffu, bi, o);
            if (ov > bv || (ov == bv && oi < bi)) { bv = ov; bi = oi; }
        }
        if (lv == bv && li == bi) cv[ls] = -3e38f;   // unique owner clears
        const int n = bi;
        if (n < 0 || n >= N) continue;               // pad / empty slots

        // exact fp32 re-score (reference op order)
        const float4* m4 = (const float4*)(mem + (size_t)n * DDIM);
        float4 ma = m4[lane], mb = m4[lane + 32];
        float ms = ma.x*ma.x + ma.y*ma.y + ma.z*ma.z + ma.w*ma.w
                 + mb.x*mb.x + mb.y*mb.y + mb.z*mb.z + mb.w*mb.w;
        #pragma unroll
        for (int o = 16; o > 0; o >>= 1) ms += __shfl_xor_sync(0xffffffffu, ms, o);
        float mn = fmaxf(sqrtf(ms), 1e-12f);
        float d = qa.x*(ma.x/mn) + qa.y*(ma.y/mn) + qa.z*(ma.z/mn) + qa.w*(ma.w/mn)
                + qb.x*(mb.x/mn) + qb.y*(mb.y/mn) + qb.z*(mb.z/mn) + qb.w*(mb.w/mn);
        #pragma unroll
        for (int o = 16; o > 0; o >>= 1) d += __shfl_xor_sync(0xffffffffu, d, o);

        // warp-uniform descending insertion, tie -> lower index
        #pragma unroll
        for (int i = KTOP - 1; i >= 0; --i) {
            bool above = (d > sv[i]) || (d == sv[i] && n < si[i]);
            if (above) {
                if (i < KTOP - 1) { sv[i + 1] = sv[i]; si[i + 1] = si[i]; }
                sv[i] = d; si[i] = n;
            }
        }
    }

    // write scores + gather raw rows
    #pragma unroll
    for (int r = 0; r < KTOP; ++r) {
        if (lane == 0)
            out[(size_t)B * KTOP * DDIM + (size_t)qi * KTOP + r] = sv[r];
        int n = si[r];
        if (n >= 0 && n < N) {
            const float4* src = (const float4*)(mem + (size_t)n * DDIM);
            float4* dst = (float4*)(out + ((size_t)qi * KTOP + r) * DDIM);
            dst[lane]      = src[lane];
            dst[lane + 32] = src[lane + 32];
        }
    }
}

// ---------------- entry -----------------------------------------------------
extern "C" void kernel_launch(void* const* d_in, const int* in_sizes, int n_in,
                              void* d_out, int out_size) {
    const float* query = (const float*)d_in[0];
    const float* mem   = (const float*)d_in[1];
    float* out         = (float*)d_out;
    (void)n_in; (void)out_size;

    const int B = in_sizes[0] / DDIM;            // 2048
    const int N = in_sizes[1] / DDIM;            // 100000
    const int ntiles = (N + NT - 1) / NT;        // 782
    const int nrows_pad = ntiles * NT;           // 100096

    norm_query_kernel<<<(B * 32 + 255) / 256, 256>>>(query, B);
    norm_mem_kernel<<<(nrows_pad * 32 + 255) / 256, 256>>>(mem, N, nrows_pad);

    cudaFuncSetAttribute(gemm_topk_kernel,
                         cudaFuncAttributeMaxDynamicSharedMemorySize, SMEM_BYTES);
    dim3 grid(B / QT, NSPLIT);
    gemm_topk_kernel<<<grid, 256, SMEM_BYTES>>>(ntiles);

    rerank_kernel<<<(B + 7) / 8, 256>>>(query, mem, out, B, N);
}

// round 7
// speedup vs baseline: 6.1777x; 1.0471x over previous
#include <cuda_runtime.h>
#include <cuda_bf16.h>
#include <cuda_fp8.h>
#include <math.h>
#include <stdint.h>

// ---------------- problem constants ----------------------------------------
#define DDIM   256
#define KTOP   8
#define CDEP   4            // per-thread per-row candidate depth (gemm)
#define CPS    32           // candidates per (query, split)
#define CTOP   32           // merged candidates re-ranked exactly in fp32
#define QT     128          // queries per CTA (M)
#define NT     128          // memory rows per tile (N)
#define NSPLIT 18           // 16 x 18 = 288 CTAs; 2 CTA/SM
#define NPAD_MAX 100096
#define BQ_MAX   2048

// ---------------- device scratch (static, no dynamic alloc) ----------------
__device__ uint8_t g_qe[(size_t)BQ_MAX   * DDIM];   // normalized queries, e4m3 x16
__device__ uint8_t g_me[(size_t)NPAD_MAX * DDIM];   // normalized memory,  e4m3 x16
__device__ float   g_minv[NPAD_MAX];                // 1/max(||m||, eps)
__device__ float g_cand_val[(size_t)BQ_MAX * NSPLIT * CPS];
__device__ int   g_cand_idx[(size_t)BQ_MAX * NSPLIT * CPS];

// ---------------- PTX helpers (plain-target instructions only) -------------
__device__ __forceinline__ uint32_t smem_to_u32(const void* p) {
    uint32_t a;
    asm("{ .reg .u64 t; cvta.to.shared.u64 t, %1; cvt.u32.u64 %0, t; }"
        : "=r"(a) : "l"(p));
    return a;
}

#define CP_ASYNC16(s, g) \
    asm volatile("cp.async.cg.shared.global [%0], [%1], 16;" :: "r"(s), "l"(g))
#define CP_COMMIT() asm volatile("cp.async.commit_group;" ::: "memory")
#define CP_WAIT(n)  asm volatile("cp.async.wait_group %0;" :: "n"(n) : "memory")

__device__ __forceinline__ void ldsm4(uint32_t* r, uint32_t a) {
    asm volatile("ldmatrix.sync.aligned.m8n8.x4.shared.b16 {%0,%1,%2,%3}, [%4];"
        : "=r"(r[0]), "=r"(r[1]), "=r"(r[2]), "=r"(r[3]) : "r"(a));
}

// fp8 e4m3 MMA: D(16x8,f32) += A(16x32) * B(32x8)
__device__ __forceinline__ void mma16832(float* d, const uint32_t* a,
                                         uint32_t b0, uint32_t b1) {
    asm volatile(
        "mma.sync.aligned.m16n8k32.row.col.f32.e4m3.e4m3.f32 "
        "{%0,%1,%2,%3}, {%4,%5,%6,%7}, {%8,%9}, {%0,%1,%2,%3};"
        : "+f"(d[0]), "+f"(d[1]), "+f"(d[2]), "+f"(d[3])
        : "r"(a[0]), "r"(a[1]), "r"(a[2]), "r"(a[3]), "r"(b0), "r"(b1));
}

// ---------------- fused normalize: mem + query rows, one launch ------------
__device__ __forceinline__ uint32_t pack_e4m3x4(float x, float y, float z, float w) {
    __nv_fp8x4_e4m3 p(make_float4(x, y, z, w));
    return *reinterpret_cast<uint32_t*>(&p);
}

__global__ void norm_kernel(const float* __restrict__ q,
                            const float* __restrict__ m,
                            int B, int Nvalid, int Ntot) {
    const int warp = (blockIdx.x * blockDim.x + threadIdx.x) >> 5;
    const int lane = threadIdx.x & 31;
    const bool is_mem = warp < Ntot;
    if (!is_mem && warp - Ntot >= B) return;

    const int row = is_mem ? warp : warp - Ntot;
    if (is_mem && row >= Nvalid) {   // zero pad rows
        uint32_t* dst = (uint32_t*)(g_me + (size_t)row * DDIM);
        dst[lane] = 0u; dst[lane + 32] = 0u;
        if (lane == 0) g_minv[row] = 0.f;
        return;
    }
    const float* in = is_mem ? m : q;
    uint32_t* dst = (uint32_t*)((is_mem ? g_me : g_qe) + (size_t)row * DDIM);

    const float4* src = (const float4*)(in + (size_t)row * DDIM);
    float4 a = src[lane];
    float4 b = src[lane + 32];
    float ss = a.x*a.x + a.y*a.y + a.z*a.z + a.w*a.w
             + b.x*b.x + b.y*b.y + b.z*b.z + b.w*b.w;
    #pragma unroll
    for (int o = 16; o > 0; o >>= 1) ss += __shfl_xor_sync(0xffffffffu, ss, o);
    float invn = 1.0f / fmaxf(sqrtf(ss), 1e-12f);
    float inv  = 16.0f * invn;                    // x16 centers e4m3 range
    dst[lane]      = pack_e4m3x4(a.x*inv, a.y*inv, a.z*inv, a.w*inv);
    dst[lane + 32] = pack_e4m3x4(b.x*inv, b.y*inv, b.z*inv, b.w*inv);
    if (is_mem && lane == 0) g_minv[row] = invn;
}

// ---------------- top-L insertion (ascending, v[0]=min) --------------------
template <int L>
__device__ __forceinline__ void insL(float s, int n, float* v, int* id) {
    #pragma unroll
    for (int i = 0; i < L; ++i) {
        if (s > v[i]) {
            bool up = (i < L - 1) && (s > v[i + 1]);
            float nv = up ? v[i + 1] : s;
            int   ni = up ? id[i + 1] : n;
            v[i] = nv; id[i] = ni;
        }
    }
}

// ascending insertion with lower-index tie-break ("better" = >, or == and lower idx)
template <int L>
__device__ __forceinline__ void insL_tie(float s, int n, float* v, int* id) {
    #pragma unroll
    for (int i = 0; i < L; ++i) {
        bool better = (s > v[i]) || (s == v[i] && n < id[i]);
        if (better) {
            bool up = (i < L - 1) && ((s > v[i + 1]) || (s == v[i + 1] && n < id[i + 1]));
            float nv = up ? v[i + 1] : s;
            int   ni = up ? id[i + 1] : n;
            v[i] = nv; id[i] = ni;
        }
    }
}

// ---------------- fused fp8 QMMA GEMM + fragment-direct top-4 --------------
// smem: A resident 32KB + B double buffer 2x32KB  -> 2 CTAs/SM
#define SA    0
#define SB0   32768
#define SB1   65536
#define SMEM_BYTES 98304

__device__ __forceinline__ void load_tile8(uint32_t sbuf, const uint8_t* g, int tid) {
    #pragma unroll
    for (int j = 0; j < 8; ++j) {
        int c_lin = j * 256 + tid;          // 2048 16B chunks
        int row = c_lin >> 4;
        int c   = c_lin & 15;
        uint32_t sw = (uint32_t)(((c ^ row) & 7) | (c & 8));
        CP_ASYNC16(sbuf + (uint32_t)(row * 256) + (sw << 4),
                   g + (size_t)row * 256 + c * 16);
    }
}

__global__ __launch_bounds__(256, 2)
void gemm_topk_kernel(int ntiles) {
    extern __shared__ __align__(16) char smem[];
    const uint32_t sb = smem_to_u32(smem);
    const int tid  = threadIdx.x, lane = tid & 31, wid = tid >> 5;
    const int wm   = wid >> 1, wn = wid & 1;            // 4 x 2 warp grid
    const int m0   = blockIdx.x * QT, split = blockIdx.y;
    const int t0   = (split * ntiles) / NSPLIT;
    const int t1   = ((split + 1) * ntiles) / NSPLIT;

    const int rA = wm * 32 + (lane & 15);
    const int rB = wn * 64 + (lane & 15);
    const int ch = lane >> 4;
    const int xA = rA & 7, xB = rB & 7;

    float cv[4][CDEP]; int ci[4][CDEP];
    #pragma unroll
    for (int r = 0; r < 4; ++r)
        #pragma unroll
        for (int i = 0; i < CDEP; ++i) { cv[r][i] = -3e38f; ci[r][i] = 0x7fffffff; }

    load_tile8(sb + SA, g_qe + (size_t)m0 * DDIM, tid);
    load_tile8(sb + SB0, g_me + (size_t)t0 * NT * DDIM, tid);
    CP_COMMIT();

    const int colbase = wn * 64 + ((lane & 3) << 1);

    for (int t = t0; t < t1; ++t) {
        const int p = (t - t0) & 1;
        const uint32_t bufB = sb + (p ? SB1 : SB0);

        CP_WAIT(0);
        __syncthreads();
        if (t + 1 < t1) {
            load_tile8(sb + (p ? SB0 : SB1), g_me + (size_t)(t + 1) * NT * DDIM, tid);
            CP_COMMIT();
        }

        float acc[2][8][4];
        #pragma unroll
        for (int mi = 0; mi < 2; ++mi)
            #pragma unroll
            for (int nj = 0; nj < 8; ++nj)
                #pragma unroll
                for (int e = 0; e < 4; ++e) acc[mi][nj][e] = 0.f;

        const uint32_t bufA = sb + SA;
        #pragma unroll
        for (int ks = 0; ks < 8; ++ks) {
            const int c = ks * 2 + ch;
            const uint32_t swA = (uint32_t)((((c ^ xA) & 7) | (c & 8)) << 4);
            const uint32_t swB = (uint32_t)((((c ^ xB) & 7) | (c & 8)) << 4);
            uint32_t a0[4], a1[4], bfr[4][4];
            ldsm4(a0, bufA + (uint32_t)(rA * 256) + swA);
            ldsm4(a1, bufA + (uint32_t)((rA + 16) * 256) + swA);
            #pragma unroll
            for (int g = 0; g < 4; ++g)
                ldsm4(bfr[g], bufB + (uint32_t)((rB + g * 16) * 256) + swB);
            #pragma unroll
            for (int g = 0; g < 4; ++g) {
                mma16832(acc[0][2*g],     a0, bfr[g][0], bfr[g][2]);
                mma16832(acc[0][2*g + 1], a0, bfr[g][1], bfr[g][3]);
                mma16832(acc[1][2*g],     a1, bfr[g][0], bfr[g][2]);
                mma16832(acc[1][2*g + 1], a1, bfr[g][1], bfr[g][3]);
            }
        }

        const int nb = t * NT + colbase;
        #pragma unroll
        for (int mi = 0; mi < 2; ++mi)
            #pragma unroll
            for (int nj = 0; nj < 8; ++nj) {
                const int n0 = nb + nj * 8;
                float* a = acc[mi][nj];
                if (a[0] > cv[2*mi][0])     insL<CDEP>(a[0], n0,     cv[2*mi],     ci[2*mi]);
                if (a[1] > cv[2*mi][0])     insL<CDEP>(a[1], n0 + 1, cv[2*mi],     ci[2*mi]);
                if (a[2] > cv[2*mi + 1][0]) insL<CDEP>(a[2], n0,     cv[2*mi + 1], ci[2*mi + 1]);
                if (a[3] > cv[2*mi + 1][0]) insL<CDEP>(a[3], n0 + 1, cv[2*mi + 1], ci[2*mi + 1]);
            }
    }

    {
        const int er   = wm * 32 + (lane >> 2);
        const int slot = wn * 4 + (lane & 3);
        #pragma unroll
        for (int r = 0; r < 4; ++r) {
            const int qrow = m0 + er + (r >> 1) * 16 + (r & 1) * 8;
            const size_t base = ((size_t)qrow * NSPLIT + split) * CPS + slot * CDEP;
            #pragma unroll
            for (int i = 0; i < CDEP; ++i) {
                g_cand_val[base + i] = cv[r][i];
                g_cand_idx[base + i] = ci[r][i];
            }
        }
    }
}

// ---------------- rerank: phase-split selection + pipelined exact scoring --
#define CANDN (NSPLIT * CPS)   // 576
#define CSLOT (CANDN / 32)     // 18
#define LDEP  8                // per-lane sorted depth (union 256 >= any top-32)

__global__ void rerank_kernel(const float* __restrict__ q,
                              const float* __restrict__ mem,
                              float* __restrict__ out, int B, int N) {
    const int lane = threadIdx.x & 31;
    const int w    = threadIdx.x >> 5;
    const int qi   = blockIdx.x * 8 + w;
    if (qi >= B) return;

    __shared__ int s_idx[8][CTOP];

    // ---- phase A: per-lane sorted top-8, then 32 pop-max extractions -----
    {
        float hv[LDEP]; int hi[LDEP];
        #pragma unroll
        for (int i = 0; i < LDEP; ++i) { hv[i] = -3e38f; hi[i] = 0x7fffffff; }
        const size_t cb = (size_t)qi * CANDN;
        #pragma unroll
        for (int j = 0; j < CSLOT; ++j) {
            int c = lane + j * 32;
            float s = g_cand_val[cb + c];
            int   n = g_cand_idx[cb + c];
            bool better0 = (s > hv[0]) || (s == hv[0] && n < hi[0]);
            if (better0) insL_tie<LDEP>(s, n, hv, hi);
        }
        #pragma unroll 1
        for (int r = 0; r < CTOP; ++r) {
            float mv = hv[LDEP - 1]; int mi = hi[LDEP - 1];
            float bv = mv; int bi = mi;
            #pragma unroll
            for (int o = 16; o > 0; o >>= 1) {
                float ov = __shfl_xor_sync(0xffffffffu, bv, o);
                int   oi = __shfl_xor_sync(0xffffffffu, bi, o);
                if (ov > bv || (ov == bv && oi < bi)) { bv = ov; bi = oi; }
            }
            if (mv == bv && mi == bi) {   // winner lane pops its max
                #pragma unroll
                for (int i = LDEP - 1; i > 0; --i) { hv[i] = hv[i - 1]; hi[i] = hi[i - 1]; }
                hv[0] = -3e38f; hi[0] = 0x7fffffff;
            }
            if (lane == 0) s_idx[w][r] = bi;
        }
        __syncwarp();
    }

    // ---- normalized query in registers -----------------------------------
    const float4* q4 = (const float4*)(q + (size_t)qi * DDIM);
    float4 qa = q4[lane], qb = q4[lane + 32];
    float qs = qa.x*qa.x + qa.y*qa.y + qa.z*qa.z + qa.w*qa.w
             + qb.x*qb.x + qb.y*qb.y + qb.z*qb.z + qb.w*qb.w;
    #pragma unroll
    for (int o = 16; o > 0; o >>= 1) qs += __shfl_xor_sync(0xffffffffu, qs, o);
    float qn = fmaxf(sqrtf(qs), 1e-12f);
    qa.x /= qn; qa.y /= qn; qa.z /= qn; qa.w /= qn;
    qb.x /= qn; qb.y /= qn; qb.z /= qn; qb.w /= qn;

    // ---- phase B: pipelined exact fp32 scoring of the 32 candidates ------
    float sv[KTOP]; int si[KTOP];
    #pragma unroll
    for (int i = 0; i < KTOP; ++i) { sv[i] = -3e38f; si[i] = 0x7fffffff; }

    int   n_cur  = s_idx[w][0];
    bool  ok_cur = (unsigned)n_cur < (unsigned)N;
    float4 ma, mb; float iv;
    {
        const float4* m4 = (const float4*)(mem + (size_t)(ok_cur ? n_cur : 0) * DDIM);
        ma = ok_cur ? m4[lane] : make_float4(0,0,0,0);
        mb = ok_cur ? m4[lane + 32] : make_float4(0,0,0,0);
        iv = ok_cur ? g_minv[n_cur] : 0.f;
    }

    #pragma unroll 1
    for (int c = 0; c < CTOP; ++c) {
        float4 cma = ma, cmb = mb; float civ = iv;
        const int  n  = n_cur;
        const bool ok = ok_cur;
        if (c + 1 < CTOP) {          // issue next loads before the reduction
            n_cur  = s_idx[w][c + 1];
            ok_cur = (unsigned)n_cur < (unsigned)N;
            const float4* m4 = (const float4*)(mem + (size_t)(ok_cur ? n_cur : 0) * DDIM);
            ma = ok_cur ? m4[lane] : make_float4(0,0,0,0);
            mb = ok_cur ? m4[lane + 32] : make_float4(0,0,0,0);
            iv = ok_cur ? g_minv[n_cur] : 0.f;
        }
        float d = qa.x*cma.x + qa.y*cma.y + qa.z*cma.z + qa.w*cma.w
                + qb.x*cmb.x + qb.y*cmb.y + qb.z*cmb.z + qb.w*cmb.w;
        #pragma unroll
        for (int o = 16; o > 0; o >>= 1) d += __shfl_xor_sync(0xffffffffu, d, o);
        d *= civ;
        if (ok) {
            #pragma unroll
            for (int i = KTOP - 1; i >= 0; --i) {
                bool above = (d > sv[i]) || (d == sv[i] && n < si[i]);
                if (above) {
                    if (i < KTOP - 1) { sv[i + 1] = sv[i]; si[i + 1] = si[i]; }
                    sv[i] = d; si[i] = n;
                }
            }
        }
    }

    // ---- write scores + gather raw rows ----------------------------------
    #pragma unroll
    for (int r = 0; r < KTOP; ++r) {
        if (lane == 0)
            out[(size_t)B * KTOP * DDIM + (size_t)qi * KTOP + r] = sv[r];
        int n = si[r];
        if ((unsigned)n < (unsigned)N) {
            const float4* src = (const float4*)(mem + (size_t)n * DDIM);
            float4* dst = (float4*)(out + ((size_t)qi * KTOP + r) * DDIM);
            dst[lane]      = src[lane];
            dst[lane + 32] = src[lane + 32];
        }
    }
}

// ---------------- entry -----------------------------------------------------
extern "C" void kernel_launch(void* const* d_in, const int* in_sizes, int n_in,
                              void* d_out, int out_size) {
    const float* query = (const float*)d_in[0];
    const float* mem   = (const float*)d_in[1];
    float* out         = (float*)d_out;
    (void)n_in; (void)out_size;

    const int B = in_sizes[0] / DDIM;            // 2048
    const int N = in_sizes[1] / DDIM;            // 100000
    const int ntiles = (N + NT - 1) / NT;        // 782
    const int nrows_pad = ntiles * NT;           // 100096

    const int total_warps = nrows_pad + B;
    norm_kernel<<<(total_warps * 32 + 255) / 256, 256>>>(query, mem, B, N, nrows_pad);

    cudaFuncSetAttribute(gemm_topk_kernel,
                         cudaFuncAttributeMaxDynamicSharedMemorySize, SMEM_BYTES);
    dim3 grid(B / QT, NSPLIT);
    gemm_topk_kernel<<<grid, 256, SMEM_BYTES>>>(ntiles);

    rerank_kernel<<<(B + 7) / 8, 256>>>(query, mem, out, B, N);
}